// round 10
// baseline (speedup 1.0000x reference)
#include <cuda_runtime.h>
#include <math.h>

#define HD 256      // hidden dim
#define BB 2        // batch
#define LL 512      // seq len (L1 == L2)
#define NHEAD 8
#define DHEAD 32
#define NSPLIT 8    // match channel splits (32 channels each)

// ---------------- scratch (device globals; no allocation) ----------------
__device__ float g_q [BB*LL*HD];                 // 1 MB
__device__ float g_k [BB*LL*HD];                 // 1 MB
__device__ float g_h1[BB*LL*HD];                 // 1 MB (includes +b1)
__device__ float g_h2[BB*LL*HD];                 // 1 MB
__device__ float g_logits[(size_t)BB*NHEAD*LL*LL]; // 16 MB; reused for match partials
__device__ float g_alpha[BB*LL];                 // sum_c (w/2) h1[b,i,c]
__device__ float g_beta [BB*LL];                 // sum_c (w/2) h2[b,j,c]

// ---------------- packed fp32x2 helpers (Blackwell) ----------------
typedef unsigned long long u64p;

__device__ __forceinline__ u64p f2_pack(float lo, float hi) {
    u64p r; asm("mov.b64 %0, {%1, %2};" : "=l"(r) : "f"(lo), "f"(hi)); return r;
}
__device__ __forceinline__ void f2_unpack(u64p p, float& lo, float& hi) {
    asm("mov.b64 {%0, %1}, %2;" : "=f"(lo), "=f"(hi) : "l"(p));
}
__device__ __forceinline__ u64p f2_fma(u64p a, u64p b, u64p c) {
    u64p d; asm("fma.rn.f32x2 %0, %1, %2, %3;" : "=l"(d) : "l"(a), "l"(b), "l"(c)); return d;
}
__device__ __forceinline__ u64p f2_add(u64p a, u64p b) {
    u64p d; asm("add.rn.f32x2 %0, %1, %2;" : "=l"(d) : "l"(a), "l"(b)); return d;
}
__device__ __forceinline__ u64p f2_abs(u64p x) {
    float lo, hi; f2_unpack(x, lo, hi);
    lo = fabsf(lo); hi = fabsf(hi);
    return f2_pack(lo, hi);
}

// =========================================================================
// K1: projections.  job z: 0=q 1=k 2=h1(+b1) 3=h2
// 64x64 tile, 256 threads, 4i x 4j/thread; acc packed along j.
// A duplicated in smem (broadcast side, ~1wf), W natural j-pairs (no MOVs).
// grid (4, 16, 4) = 256 blocks.
// =========================================================================
__global__ __launch_bounds__(256) void proj_kernel(
    const float* __restrict__ e1, const float* __restrict__ e2,
    const float* __restrict__ ipw, const float* __restrict__ ipb,
    const float* __restrict__ W1,  const float* __restrict__ b1)
{
    const int job = blockIdx.z;
    const float* A; const float* W; const float* bias; int ldw; float* C;
    if (job == 0)      { A = e1; W = ipw;           bias = ipb;      ldw = HD;   C = g_q;  }
    else if (job == 1) { A = e2; W = ipw + HD*HD;   bias = ipb + HD; ldw = HD;   C = g_k;  }
    else if (job == 2) { A = e1; W = W1;            bias = b1;       ldw = 2*HD; C = g_h1; }
    else               { A = e2; W = W1 + HD;       bias = nullptr;  ldw = 2*HD; C = g_h2; }

    const int i0 = blockIdx.y * 64;
    const int j0 = blockIdx.x * 64;

    __shared__ __align__(16) float sAd[32][132];  // [kk][2i] duplicated, 128 used
    __shared__ __align__(16) float sW [32][68];   // [kk][j] natural, 64 used

    const int tid = threadIdx.x;
    const int ty = tid >> 4;       // rows i0+ty*4 .. +3
    const int tx = tid & 15;       // cols j0+tx*4 .. +3 (2 pairs)

    u64p acc[4][2] = {};   // [row u][j-pair q]

    for (int k0 = 0; k0 < HD; k0 += 32) {
        float4 va[2], vw[2];
        int row_[2], kq[2];
#pragma unroll
        for (int r = 0; r < 2; r++) {
            int pidx = tid + r * 256;
            row_[r] = pidx >> 3; kq[r] = (pidx & 7) << 2;
            va[r] = *(const float4*)&A[(size_t)(i0 + row_[r]) * HD  + k0 + kq[r]];
            vw[r] = *(const float4*)&W[(size_t)(j0 + row_[r]) * ldw + k0 + kq[r]];
        }
        __syncthreads();
#pragma unroll
        for (int r = 0; r < 2; r++) {
            *(float2*)&sAd[kq[r]+0][2*row_[r]] = make_float2(va[r].x, va[r].x);
            *(float2*)&sAd[kq[r]+1][2*row_[r]] = make_float2(va[r].y, va[r].y);
            *(float2*)&sAd[kq[r]+2][2*row_[r]] = make_float2(va[r].z, va[r].z);
            *(float2*)&sAd[kq[r]+3][2*row_[r]] = make_float2(va[r].w, va[r].w);
            sW[kq[r]+0][row_[r]] = vw[r].x; sW[kq[r]+1][row_[r]] = vw[r].y;
            sW[kq[r]+2][row_[r]] = vw[r].z; sW[kq[r]+3][row_[r]] = vw[r].w;
        }
        __syncthreads();

#pragma unroll
        for (int kk = 0; kk < 32; kk++) {
            const ulonglong2 a01 = *(const ulonglong2*)&sAd[kk][ty*8];      // (a0,a0),(a1,a1)
            const ulonglong2 a23 = *(const ulonglong2*)&sAd[kk][ty*8 + 4];  // (a2,a2),(a3,a3)
            const ulonglong2 wp  = *(const ulonglong2*)&sW [kk][tx*4];      // (w0,w1),(w2,w3)
            acc[0][0] = f2_fma(a01.x, wp.x, acc[0][0]);
            acc[0][1] = f2_fma(a01.x, wp.y, acc[0][1]);
            acc[1][0] = f2_fma(a01.y, wp.x, acc[1][0]);
            acc[1][1] = f2_fma(a01.y, wp.y, acc[1][1]);
            acc[2][0] = f2_fma(a23.x, wp.x, acc[2][0]);
            acc[2][1] = f2_fma(a23.x, wp.y, acc[2][1]);
            acc[3][0] = f2_fma(a23.y, wp.x, acc[3][0]);
            acc[3][1] = f2_fma(a23.y, wp.y, acc[3][1]);
        }
        __syncthreads();
    }

    float bv[4] = {0.f, 0.f, 0.f, 0.f};
    if (bias) {
        float4 b4 = *(const float4*)&bias[j0 + tx*4];
        bv[0] = b4.x; bv[1] = b4.y; bv[2] = b4.z; bv[3] = b4.w;
    }
#pragma unroll
    for (int u = 0; u < 4; u++) {
        float c0, c1, c2, c3;
        f2_unpack(acc[u][0], c0, c1);   // cols tx*4+0, +1 (same row)
        f2_unpack(acc[u][1], c2, c3);   // cols tx*4+2, +3
        float4 o4 = make_float4(c0 + bv[0], c1 + bv[1], c2 + bv[2], c3 + bv[3]);
        *(float4*)&C[(size_t)(i0 + ty*4 + u) * HD + j0 + tx*4] = o4;
    }
}

// =========================================================================
// K2: logits[b,h,i,j] = (1/sqrt(32)) * sum_d q*k.  Same j-packed structure.
// grid (8,8,16)=1024; tile 64x64, 256 threads, K=32 single chunk.
// =========================================================================
__global__ __launch_bounds__(256) void logits_kernel()
{
    const int bh = blockIdx.z;
    const int b  = bh >> 3, h = bh & 7;
    const float* Q  = g_q + (size_t)b * LL * HD + h * DHEAD;
    const float* Kp = g_k + (size_t)b * LL * HD + h * DHEAD;
    float* C = g_logits + (size_t)bh * LL * LL;

    const int i0 = blockIdx.y * 64;
    const int j0 = blockIdx.x * 64;

    __shared__ __align__(16) float sQd[32][132];  // [kk][2i] dup
    __shared__ __align__(16) float sK [32][68];   // [kk][j] natural

    const int tid = threadIdx.x;
    const int ty = tid >> 4;
    const int tx = tid & 15;

    {
        float4 vq[2], vk[2];
        int row_[2], kq[2];
#pragma unroll
        for (int r = 0; r < 2; r++) {
            int pidx = tid + r * 256;
            row_[r] = pidx >> 3; kq[r] = (pidx & 7) << 2;
            vq[r] = *(const float4*)&Q [(size_t)(i0 + row_[r]) * HD + kq[r]];
            vk[r] = *(const float4*)&Kp[(size_t)(j0 + row_[r]) * HD + kq[r]];
        }
#pragma unroll
        for (int r = 0; r < 2; r++) {
            *(float2*)&sQd[kq[r]+0][2*row_[r]] = make_float2(vq[r].x, vq[r].x);
            *(float2*)&sQd[kq[r]+1][2*row_[r]] = make_float2(vq[r].y, vq[r].y);
            *(float2*)&sQd[kq[r]+2][2*row_[r]] = make_float2(vq[r].z, vq[r].z);
            *(float2*)&sQd[kq[r]+3][2*row_[r]] = make_float2(vq[r].w, vq[r].w);
            sK[kq[r]+0][row_[r]] = vk[r].x; sK[kq[r]+1][row_[r]] = vk[r].y;
            sK[kq[r]+2][row_[r]] = vk[r].z; sK[kq[r]+3][row_[r]] = vk[r].w;
        }
    }
    __syncthreads();

    u64p acc[4][2] = {};
#pragma unroll
    for (int kk = 0; kk < 32; kk++) {
        const ulonglong2 a01 = *(const ulonglong2*)&sQd[kk][ty*8];
        const ulonglong2 a23 = *(const ulonglong2*)&sQd[kk][ty*8 + 4];
        const ulonglong2 wp  = *(const ulonglong2*)&sK [kk][tx*4];
        acc[0][0] = f2_fma(a01.x, wp.x, acc[0][0]);
        acc[0][1] = f2_fma(a01.x, wp.y, acc[0][1]);
        acc[1][0] = f2_fma(a01.y, wp.x, acc[1][0]);
        acc[1][1] = f2_fma(a01.y, wp.y, acc[1][1]);
        acc[2][0] = f2_fma(a23.x, wp.x, acc[2][0]);
        acc[2][1] = f2_fma(a23.x, wp.y, acc[2][1]);
        acc[3][0] = f2_fma(a23.y, wp.x, acc[3][0]);
        acc[3][1] = f2_fma(a23.y, wp.y, acc[3][1]);
    }

    const float scale = 0.1767766952966369f; // 1/sqrt(32)
#pragma unroll
    for (int u = 0; u < 4; u++) {
        float c0, c1, c2, c3;
        f2_unpack(acc[u][0], c0, c1);
        f2_unpack(acc[u][1], c2, c3);
        float4 o4 = make_float4(c0*scale, c1*scale, c2*scale, c3*scale);
        *(float4*)&C[(size_t)(i0 + ty*4 + u) * LL + j0 + tx*4] = o4;
    }
}

// =========================================================================
// K3: softmax + head-mean + alpha/beta (unchanged from R9).
// =========================================================================
__global__ __launch_bounds__(256) void softmax_mean_kernel(
    const float* __restrict__ W2, float* __restrict__ out)
{
    const int b = blockIdx.x >> 9;
    const int i = blockIdx.x & 511;
    const int wid  = threadIdx.x >> 5;
    const int lane = threadIdx.x & 31;
    const int t = threadIdx.x;

    __shared__ float p[8][512];
    __shared__ float reda[8], redb[8];

    const float* row = g_logits + ((size_t)(b*8 + wid) * LL + i) * LL;

    float v[16];
    float mx = -1e30f;
#pragma unroll
    for (int r = 0; r < 16; r++) {
        v[r] = row[lane + 32*r];
        mx = fmaxf(mx, v[r]);
    }
#pragma unroll
    for (int o = 16; o; o >>= 1) mx = fmaxf(mx, __shfl_xor_sync(0xffffffffu, mx, o));

    float s = 0.0f;
#pragma unroll
    for (int r = 0; r < 16; r++) { v[r] = __expf(v[r] - mx); s += v[r]; }
#pragma unroll
    for (int o = 16; o; o >>= 1) s += __shfl_xor_sync(0xffffffffu, s, o);
    const float inv = 1.0f / s;

#pragma unroll
    for (int r = 0; r < 16; r++) p[wid][lane + 32*r] = v[r] * inv;

    {
        const float wh = 0.5f * W2[t];
        float pa = g_h1[((size_t)b*LL + i)*HD + t] * wh;
        float pb = g_h2[((size_t)b*LL + i)*HD + t] * wh;
#pragma unroll
        for (int o = 16; o; o >>= 1) {
            pa += __shfl_xor_sync(0xffffffffu, pa, o);
            pb += __shfl_xor_sync(0xffffffffu, pb, o);
        }
        if (lane == 0) { reda[wid] = pa; redb[wid] = pb; }
    }

    __syncthreads();

    const size_t o = ((size_t)b * LL + i) * LL;
#pragma unroll
    for (int jj = 0; jj < 2; jj++) {
        int j = t + jj * 256;
        float a = 0.0f;
#pragma unroll
        for (int h = 0; h < 8; h++) a += p[h][j];
        out[o + j] = a * 0.125f;
    }

    if (t < 16) {
        float va = (t < 8) ? reda[t] : redb[t - 8];
#pragma unroll
        for (int oo = 4; oo; oo >>= 1) va += __shfl_xor_sync(0xffffffffu, va, oo);
        if (t == 0) g_alpha[b*LL + i] = va;
        if (t == 8) g_beta [b*LL + i] = va;
    }
}

// =========================================================================
// K4: match partials over 8 channel-splits of 32.
// P[(s*BB+b)*LL*LL + ...] = sum_{c in split} (w2[c]/2) * |h1[i,c]+h2[j,c]|
// Block tile 128i x 64j, 128 threads, 8i x 8j/thread; acc packed along j.
// A duplicated (broadcast side), B natural j-pairs, w2/2 dup.
// grid (8, 4, 16) = 512 blocks of 4 warps, 32-deep ILP per thread.
// =========================================================================
__global__ __launch_bounds__(128, 4) void match_partial_kernel(
    const float* __restrict__ W2, float* __restrict__ P)
{
    const int bz = blockIdx.z;
    const int b  = bz & 1;
    const int s  = bz >> 1;
    const int i0 = blockIdx.y * 128;
    const int j0 = blockIdx.x * 64;
    const int c0 = s * 32;

    const float* A  = g_h1 + (size_t)b * LL * HD + c0;
    const float* Bm = g_h2 + (size_t)b * LL * HD + c0;

    __shared__ __align__(16) float sAd[32][260];  // [kk][2i], 256 used (dup)
    __shared__ __align__(16) float sB [32][68];   // [kk][j], 64 used (natural)
    __shared__ __align__(16) float2 sw2d[32];     // (w/2, w/2)

    const int tid = threadIdx.x;
    const int ty = tid >> 3;       // 0..15 -> rows i0+ty*8 .. +7
    const int tx = tid & 7;        // 0..7  -> cols j0+tx*8 .. +7 (4 pairs)

    if (tid < 32) { float w = 0.5f * W2[c0 + tid]; sw2d[tid] = make_float2(w, w); }
    const u64p* swd = (const u64p*)sw2d;

    // loaders: A 128 rows x 32 ch = 1024 float4 (8/thread); B 64 rows (4/thread)
    {
        float4 va[8], vb[4];
        int ar[8], ak[8];
#pragma unroll
        for (int r = 0; r < 8; r++) {
            int pidx = tid + r * 128;
            ar[r] = pidx >> 3; ak[r] = (pidx & 7) << 2;
            va[r] = *(const float4*)&A[(size_t)(i0 + ar[r]) * HD + ak[r]];
        }
#pragma unroll
        for (int r = 0; r < 4; r++) {
            int pidx = tid + r * 128;
            vb[r] = *(const float4*)&Bm[(size_t)(j0 + (pidx >> 3)) * HD + ((pidx & 7) << 2)];
        }
#pragma unroll
        for (int r = 0; r < 8; r++) {
            *(float2*)&sAd[ak[r]+0][2*ar[r]] = make_float2(va[r].x, va[r].x);
            *(float2*)&sAd[ak[r]+1][2*ar[r]] = make_float2(va[r].y, va[r].y);
            *(float2*)&sAd[ak[r]+2][2*ar[r]] = make_float2(va[r].z, va[r].z);
            *(float2*)&sAd[ak[r]+3][2*ar[r]] = make_float2(va[r].w, va[r].w);
        }
#pragma unroll
        for (int r = 0; r < 4; r++) {
            int pidx = tid + r * 128;
            int br = pidx >> 3, bk = (pidx & 7) << 2;
            sB[bk+0][br] = vb[r].x; sB[bk+1][br] = vb[r].y;
            sB[bk+2][br] = vb[r].z; sB[bk+3][br] = vb[r].w;
        }
    }
    __syncthreads();

    u64p acc[8][4] = {};   // [i-row p][j-pair q]

#pragma unroll
    for (int kk = 0; kk < 32; kk++) {
        const ulonglong2 a01 = *(const ulonglong2*)&sAd[kk][ty*16];      // (a0,a0),(a1,a1)
        const ulonglong2 a23 = *(const ulonglong2*)&sAd[kk][ty*16 + 4];
        const ulonglong2 a45 = *(const ulonglong2*)&sAd[kk][ty*16 + 8];
        const ulonglong2 a67 = *(const ulonglong2*)&sAd[kk][ty*16 + 12];
        const ulonglong2 b03 = *(const ulonglong2*)&sB [kk][tx*8];       // (b0,b1),(b2,b3)
        const ulonglong2 b47 = *(const ulonglong2*)&sB [kk][tx*8 + 4];   // (b4,b5),(b6,b7)
        const u64p wd = swd[kk];
        u64p a[8]  = {a01.x, a01.y, a23.x, a23.y, a45.x, a45.y, a67.x, a67.y};
        u64p bp[4] = {b03.x, b03.y, b47.x, b47.y};
#pragma unroll
        for (int p = 0; p < 8; p++)
#pragma unroll
            for (int q = 0; q < 4; q++)
                acc[p][q] = f2_fma(f2_abs(f2_add(a[p], bp[q])), wd, acc[p][q]);
    }

    float* Pd = P + ((size_t)(s*BB + b) * LL * LL);
#pragma unroll
    for (int p = 0; p < 8; p++) {
        float c[8];
        f2_unpack(acc[p][0], c[0], c[1]);
        f2_unpack(acc[p][1], c[2], c[3]);
        f2_unpack(acc[p][2], c[4], c[5]);
        f2_unpack(acc[p][3], c[6], c[7]);
        float* dst = &Pd[(size_t)(i0 + ty*8 + p) * LL + j0 + tx*8];
        *(float4*)&dst[0] = make_float4(c[0], c[1], c[2], c[3]);
        *(float4*)&dst[4] = make_float4(c[4], c[5], c[6], c[7]);
    }
}

// =========================================================================
// K5: combine: out = sigmoid(alpha_i + beta_j + sum_s P_s + b2)
// =========================================================================
__global__ __launch_bounds__(256) void combine_kernel(
    const float* __restrict__ P, const float* __restrict__ b2,
    float* __restrict__ out)
{
    const size_t n = (size_t)BB * LL * LL;
    const size_t idx = ((size_t)blockIdx.x * 256 + threadIdx.x) * 4;
    if (idx >= n) return;

    const int b = (int)(idx >> 18);
    const int rem = (int)(idx & 262143);
    const int i = rem >> 9;
    const int j = rem & 511;

    float base = g_alpha[b*LL + i] + b2[0];
    float4 bt = *(const float4*)&g_beta[b*LL + j];

    float4 acc = make_float4(base + bt.x, base + bt.y, base + bt.z, base + bt.w);
#pragma unroll
    for (int s = 0; s < NSPLIT; s++) {
        float4 ps = *(const float4*)&P[(size_t)s * n + idx];
        acc.x += ps.x; acc.y += ps.y; acc.z += ps.z; acc.w += ps.w;
    }
    float4 o;
    o.x = 1.0f / (1.0f + __expf(-acc.x));
    o.y = 1.0f / (1.0f + __expf(-acc.y));
    o.z = 1.0f / (1.0f + __expf(-acc.z));
    o.w = 1.0f / (1.0f + __expf(-acc.w));
    *(float4*)&out[n + idx] = o;
}

// =========================================================================
extern "C" void kernel_launch(void* const* d_in, const int* in_sizes, int n_in,
                              void* d_out, int out_size)
{
    const float* e1  = (const float*)d_in[0];  // (B,L1,H)
    const float* e2  = (const float*)d_in[1];  // (B,L2,H)
    const float* ipw = (const float*)d_in[2];  // (3H,H)
    const float* ipb = (const float*)d_in[3];  // (3H,)
    const float* W1  = (const float*)d_in[4];  // (H,2H)
    const float* b1  = (const float*)d_in[5];  // (H,)
    const float* W2  = (const float*)d_in[6];  // (1,H)
    const float* b2  = (const float*)d_in[7];  // (1,)
    float* out = (float*)d_out;                // [attn (B,L1,L2)] ++ [match (B,L1,L2)]

    float* P;
    cudaGetSymbolAddress((void**)&P, g_logits);   // reuse logits buffer for partials

    proj_kernel   <<<dim3(HD/64, (BB*LL)/64, 4), 256>>>(e1, e2, ipw, ipb, W1, b1);
    logits_kernel <<<dim3(LL/64, LL/64, BB*NHEAD), 256>>>();
    softmax_mean_kernel<<<BB*LL, 256>>>(W2, out);
    match_partial_kernel<<<dim3(LL/64, LL/128, BB*NSPLIT), 128>>>(W2, P);
    combine_kernel<<<(unsigned)((BB*LL*LL/4 + 255)/256), 256>>>(P, b2, out);
}

// round 11
// speedup vs baseline: 1.1826x; 1.1826x over previous
#include <cuda_runtime.h>
#include <math.h>

#define HD 256      // hidden dim
#define BB 2        // batch
#define LL 512      // seq len (L1 == L2)
#define NHEAD 8
#define DHEAD 32
#define NSPLIT 8    // match channel splits (32 channels each)

// ---------------- scratch (device globals; no allocation) ----------------
__device__ float g_q [BB*LL*HD];                 // 1 MB
__device__ float g_k [BB*LL*HD];                 // 1 MB
__device__ float g_h1[BB*LL*HD];                 // 1 MB (includes +b1)
__device__ float g_h2[BB*LL*HD];                 // 1 MB
__device__ float g_logits[(size_t)BB*NHEAD*LL*LL]; // 16 MB; reused for match partials
__device__ float g_alpha[BB*LL];                 // sum_c (w/2) h1[b,i,c]
__device__ float g_beta [BB*LL];                 // sum_c (w/2) h2[b,j,c]

// ---------------- packed fp32x2 helpers (Blackwell) ----------------
typedef unsigned long long u64p;

__device__ __forceinline__ u64p f2_pack(float lo, float hi) {
    u64p r; asm("mov.b64 %0, {%1, %2};" : "=l"(r) : "f"(lo), "f"(hi)); return r;
}
__device__ __forceinline__ void f2_unpack(u64p p, float& lo, float& hi) {
    asm("mov.b64 {%0, %1}, %2;" : "=f"(lo), "=f"(hi) : "l"(p));
}
__device__ __forceinline__ u64p f2_fma(u64p a, u64p b, u64p c) {
    u64p d; asm("fma.rn.f32x2 %0, %1, %2, %3;" : "=l"(d) : "l"(a), "l"(b), "l"(c)); return d;
}
__device__ __forceinline__ u64p f2_add(u64p a, u64p b) {
    u64p d; asm("add.rn.f32x2 %0, %1, %2;" : "=l"(d) : "l"(a), "l"(b)); return d;
}
__device__ __forceinline__ u64p f2_abs(u64p x) {
    float lo, hi; f2_unpack(x, lo, hi);
    lo = fabsf(lo); hi = fabsf(hi);
    return f2_pack(lo, hi);
}

#define SMS 36   // smem row stride (floats): granule stride 9 (odd) -> conflict-free

// =========================================================================
// K1: projections (K-packed).  job z: 0=q 1=k 2=h1(+b1) 3=h2
// 64x64 tile, 256 threads, 4i x 4j/thread; f32x2 packed along K.
// Row-major smem [row][k]; natural LDS.128 k-quads both sides; no MOVs.
// grid (4, 16, 4) = 256 blocks.
// =========================================================================
__global__ __launch_bounds__(256) void proj_kernel(
    const float* __restrict__ e1, const float* __restrict__ e2,
    const float* __restrict__ ipw, const float* __restrict__ ipb,
    const float* __restrict__ W1,  const float* __restrict__ b1)
{
    const int job = blockIdx.z;
    const float* A; const float* W; const float* bias; int ldw; float* C;
    if (job == 0)      { A = e1; W = ipw;           bias = ipb;      ldw = HD;   C = g_q;  }
    else if (job == 1) { A = e2; W = ipw + HD*HD;   bias = ipb + HD; ldw = HD;   C = g_k;  }
    else if (job == 2) { A = e1; W = W1;            bias = b1;       ldw = 2*HD; C = g_h1; }
    else               { A = e2; W = W1 + HD;       bias = nullptr;  ldw = 2*HD; C = g_h2; }

    const int i0 = blockIdx.y * 64;
    const int j0 = blockIdx.x * 64;

    __shared__ __align__(16) float sA[64][SMS];   // [i-row][k] 32 k used
    __shared__ __align__(16) float sW[64][SMS];   // [j-row][k]

    const int tid = threadIdx.x;
    const int ty = tid >> 4;       // rows i0 + ty*4 + u
    const int tx = tid & 15;       // cols j0 + tx + 16*v

    u64p acc[4][4] = {};   // [u][v], packed over k-parity

    for (int k0 = 0; k0 < HD; k0 += 32) {
        float4 va[2], vw[2];
        int row_[2], kq[2];
#pragma unroll
        for (int r = 0; r < 2; r++) {
            int pidx = tid + r * 256;
            row_[r] = pidx >> 3; kq[r] = (pidx & 7) << 2;
            va[r] = *(const float4*)&A[(size_t)(i0 + row_[r]) * HD  + k0 + kq[r]];
            vw[r] = *(const float4*)&W[(size_t)(j0 + row_[r]) * ldw + k0 + kq[r]];
        }
        __syncthreads();
#pragma unroll
        for (int r = 0; r < 2; r++) {
            *(float4*)&sA[row_[r]][kq[r]] = va[r];
            *(float4*)&sW[row_[r]][kq[r]] = vw[r];
        }
        __syncthreads();

#pragma unroll
        for (int kk4 = 0; kk4 < 32; kk4 += 4) {
            ulonglong2 a[4], w[4];
#pragma unroll
            for (int u = 0; u < 4; u++) a[u] = *(const ulonglong2*)&sA[ty*4 + u][kk4];
#pragma unroll
            for (int v = 0; v < 4; v++) w[v] = *(const ulonglong2*)&sW[tx + 16*v][kk4];
#pragma unroll
            for (int u = 0; u < 4; u++)
#pragma unroll
                for (int v = 0; v < 4; v++) {
                    acc[u][v] = f2_fma(a[u].x, w[v].x, acc[u][v]);
                    acc[u][v] = f2_fma(a[u].y, w[v].y, acc[u][v]);
                }
        }
        __syncthreads();
    }

    float bv[4] = {0.f, 0.f, 0.f, 0.f};
    if (bias) {
#pragma unroll
        for (int v = 0; v < 4; v++) bv[v] = bias[j0 + tx + 16*v];
    }
#pragma unroll
    for (int u = 0; u < 4; u++) {
        const size_t rowoff = (size_t)(i0 + ty*4 + u) * HD + j0 + tx;
#pragma unroll
        for (int v = 0; v < 4; v++) {
            float lo, hi;
            f2_unpack(acc[u][v], lo, hi);
            C[rowoff + 16*v] = lo + hi + bv[v];
        }
    }
}

// =========================================================================
// K2: logits (K-packed). grid (8,8,16); tile 64x64, K=32 single chunk.
// =========================================================================
__global__ __launch_bounds__(256) void logits_kernel()
{
    const int bh = blockIdx.z;
    const int b  = bh >> 3, h = bh & 7;
    const float* Q  = g_q + (size_t)b * LL * HD + h * DHEAD;
    const float* Kp = g_k + (size_t)b * LL * HD + h * DHEAD;
    float* C = g_logits + (size_t)bh * LL * LL;

    const int i0 = blockIdx.y * 64;
    const int j0 = blockIdx.x * 64;

    __shared__ __align__(16) float sQ[64][SMS];
    __shared__ __align__(16) float sK[64][SMS];

    const int tid = threadIdx.x;
    const int ty = tid >> 4;
    const int tx = tid & 15;

    {
        float4 vq[2], vk[2];
        int row_[2], kq[2];
#pragma unroll
        for (int r = 0; r < 2; r++) {
            int pidx = tid + r * 256;
            row_[r] = pidx >> 3; kq[r] = (pidx & 7) << 2;
            vq[r] = *(const float4*)&Q [(size_t)(i0 + row_[r]) * HD + kq[r]];
            vk[r] = *(const float4*)&Kp[(size_t)(j0 + row_[r]) * HD + kq[r]];
        }
#pragma unroll
        for (int r = 0; r < 2; r++) {
            *(float4*)&sQ[row_[r]][kq[r]] = vq[r];
            *(float4*)&sK[row_[r]][kq[r]] = vk[r];
        }
    }
    __syncthreads();

    u64p acc[4][4] = {};
#pragma unroll
    for (int kk4 = 0; kk4 < 32; kk4 += 4) {
        ulonglong2 a[4], w[4];
#pragma unroll
        for (int u = 0; u < 4; u++) a[u] = *(const ulonglong2*)&sQ[ty*4 + u][kk4];
#pragma unroll
        for (int v = 0; v < 4; v++) w[v] = *(const ulonglong2*)&sK[tx + 16*v][kk4];
#pragma unroll
        for (int u = 0; u < 4; u++)
#pragma unroll
            for (int v = 0; v < 4; v++) {
                acc[u][v] = f2_fma(a[u].x, w[v].x, acc[u][v]);
                acc[u][v] = f2_fma(a[u].y, w[v].y, acc[u][v]);
            }
    }

    const float scale = 0.1767766952966369f; // 1/sqrt(32)
#pragma unroll
    for (int u = 0; u < 4; u++) {
        const size_t rowoff = (size_t)(i0 + ty*4 + u) * LL + j0 + tx;
#pragma unroll
        for (int v = 0; v < 4; v++) {
            float lo, hi;
            f2_unpack(acc[u][v], lo, hi);
            C[rowoff + 16*v] = (lo + hi) * scale;
        }
    }
}

// =========================================================================
// K3: softmax + head-mean + alpha/beta (R9 verbatim).
// =========================================================================
__global__ __launch_bounds__(256) void softmax_mean_kernel(
    const float* __restrict__ W2, float* __restrict__ out)
{
    const int b = blockIdx.x >> 9;
    const int i = blockIdx.x & 511;
    const int wid  = threadIdx.x >> 5;
    const int lane = threadIdx.x & 31;
    const int t = threadIdx.x;

    __shared__ float p[8][512];
    __shared__ float reda[8], redb[8];

    const float* row = g_logits + ((size_t)(b*8 + wid) * LL + i) * LL;

    float v[16];
    float mx = -1e30f;
#pragma unroll
    for (int r = 0; r < 16; r++) {
        v[r] = row[lane + 32*r];
        mx = fmaxf(mx, v[r]);
    }
#pragma unroll
    for (int o = 16; o; o >>= 1) mx = fmaxf(mx, __shfl_xor_sync(0xffffffffu, mx, o));

    float s = 0.0f;
#pragma unroll
    for (int r = 0; r < 16; r++) { v[r] = __expf(v[r] - mx); s += v[r]; }
#pragma unroll
    for (int o = 16; o; o >>= 1) s += __shfl_xor_sync(0xffffffffu, s, o);
    const float inv = 1.0f / s;

#pragma unroll
    for (int r = 0; r < 16; r++) p[wid][lane + 32*r] = v[r] * inv;

    {
        const float wh = 0.5f * W2[t];
        float pa = g_h1[((size_t)b*LL + i)*HD + t] * wh;
        float pb = g_h2[((size_t)b*LL + i)*HD + t] * wh;
#pragma unroll
        for (int o = 16; o; o >>= 1) {
            pa += __shfl_xor_sync(0xffffffffu, pa, o);
            pb += __shfl_xor_sync(0xffffffffu, pb, o);
        }
        if (lane == 0) { reda[wid] = pa; redb[wid] = pb; }
    }

    __syncthreads();

    const size_t o = ((size_t)b * LL + i) * LL;
#pragma unroll
    for (int jj = 0; jj < 2; jj++) {
        int j = t + jj * 256;
        float a = 0.0f;
#pragma unroll
        for (int h = 0; h < 8; h++) a += p[h][j];
        out[o + j] = a * 0.125f;
    }

    if (t < 16) {
        float va = (t < 8) ? reda[t] : redb[t - 8];
#pragma unroll
        for (int oo = 4; oo; oo >>= 1) va += __shfl_xor_sync(0xffffffffu, va, oo);
        if (t == 0) g_alpha[b*LL + i] = va;
        if (t == 8) g_beta [b*LL + i] = va;
    }
}

// =========================================================================
// K4: match partials (R9 verbatim). 8 splits of 32 channels.
// Block tile 64i x 64j, 128 threads, 8i x 4j/thread (i-packed pairs).
// grid (8, 8, 16) = 1024 blocks of 4 warps.
// =========================================================================
__global__ __launch_bounds__(128) void match_partial_kernel(
    const float* __restrict__ W2, float* __restrict__ P)
{
    const int bz = blockIdx.z;
    const int b  = bz & 1;
    const int s  = bz >> 1;
    const int i0 = blockIdx.y * 64;
    const int j0 = blockIdx.x * 64;
    const int c0 = s * 32;

    const float* A  = g_h1 + (size_t)b * LL * HD + c0;
    const float* Bm = g_h2 + (size_t)b * LL * HD + c0;

    __shared__ __align__(16) float sA [32][68];   // [kk][i], 64 used (natural)
    __shared__ __align__(16) float sBd[32][132];  // [kk][2j], 128 used (dup)
    __shared__ __align__(16) float2 sw2d[32];     // (w/2, w/2)

    const int tid = threadIdx.x;
    const int ty = tid >> 4;       // 0..7  -> rows ty*8 .. ty*8+7 (4 pairs)
    const int tx = tid & 15;       // 0..15 -> cols tx*4 .. tx*4+3

    if (tid < 32) { float w = 0.5f * W2[c0 + tid]; sw2d[tid] = make_float2(w, w); }
    const u64p* swd = (const u64p*)sw2d;

    {
        float4 va[4], vb[4];
        int arow[4], ak[4];
#pragma unroll
        for (int r = 0; r < 4; r++) {
            int pidx = tid + r * 128;
            arow[r] = pidx >> 3; ak[r] = (pidx & 7) << 2;
            va[r] = *(const float4*)&A [(size_t)(i0 + arow[r]) * HD + ak[r]];
            vb[r] = *(const float4*)&Bm[(size_t)(j0 + arow[r]) * HD + ak[r]];
        }
#pragma unroll
        for (int r = 0; r < 4; r++) {
            sA[ak[r]+0][arow[r]] = va[r].x; sA[ak[r]+1][arow[r]] = va[r].y;
            sA[ak[r]+2][arow[r]] = va[r].z; sA[ak[r]+3][arow[r]] = va[r].w;
            *(float2*)&sBd[ak[r]+0][2*arow[r]] = make_float2(vb[r].x, vb[r].x);
            *(float2*)&sBd[ak[r]+1][2*arow[r]] = make_float2(vb[r].y, vb[r].y);
            *(float2*)&sBd[ak[r]+2][2*arow[r]] = make_float2(vb[r].z, vb[r].z);
            *(float2*)&sBd[ak[r]+3][2*arow[r]] = make_float2(vb[r].w, vb[r].w);
        }
    }
    __syncthreads();

    u64p acc[4][4] = {};   // [i-pair p][j]

#pragma unroll
    for (int kk = 0; kk < 32; kk++) {
        const ulonglong2 a01 = *(const ulonglong2*)&sA [kk][ty*8];
        const ulonglong2 a23 = *(const ulonglong2*)&sA [kk][ty*8 + 4];
        const ulonglong2 b01 = *(const ulonglong2*)&sBd[kk][tx*8];
        const ulonglong2 b23 = *(const ulonglong2*)&sBd[kk][tx*8 + 4];
        const u64p wd = swd[kk];
        u64p a[4]  = {a01.x, a01.y, a23.x, a23.y};
        u64p bd[4] = {b01.x, b01.y, b23.x, b23.y};
#pragma unroll
        for (int p = 0; p < 4; p++)
#pragma unroll
            for (int j = 0; j < 4; j++)
                acc[p][j] = f2_fma(f2_abs(f2_add(a[p], bd[j])), wd, acc[p][j]);
    }

    float* Pd = P + ((size_t)(s*BB + b) * LL * LL);
#pragma unroll
    for (int p = 0; p < 4; p++) {
        float lo[4], hi[4];
#pragma unroll
        for (int j = 0; j < 4; j++) f2_unpack(acc[p][j], lo[j], hi[j]);
        const int r0 = i0 + ty*8 + 2*p;
        *(float4*)&Pd[(size_t)(r0+0) * LL + j0 + tx*4] = make_float4(lo[0], lo[1], lo[2], lo[3]);
        *(float4*)&Pd[(size_t)(r0+1) * LL + j0 + tx*4] = make_float4(hi[0], hi[1], hi[2], hi[3]);
    }
}

// =========================================================================
// K5: combine: out = sigmoid(alpha_i + beta_j + sum_s P_s + b2)
// =========================================================================
__global__ __launch_bounds__(256) void combine_kernel(
    const float* __restrict__ P, const float* __restrict__ b2,
    float* __restrict__ out)
{
    const size_t n = (size_t)BB * LL * LL;
    const size_t idx = ((size_t)blockIdx.x * 256 + threadIdx.x) * 4;
    if (idx >= n) return;

    const int b = (int)(idx >> 18);
    const int rem = (int)(idx & 262143);
    const int i = rem >> 9;
    const int j = rem & 511;

    float base = g_alpha[b*LL + i] + b2[0];
    float4 bt = *(const float4*)&g_beta[b*LL + j];

    float4 acc = make_float4(base + bt.x, base + bt.y, base + bt.z, base + bt.w);
#pragma unroll
    for (int s = 0; s < NSPLIT; s++) {
        float4 ps = *(const float4*)&P[(size_t)s * n + idx];
        acc.x += ps.x; acc.y += ps.y; acc.z += ps.z; acc.w += ps.w;
    }
    float4 o;
    o.x = 1.0f / (1.0f + __expf(-acc.x));
    o.y = 1.0f / (1.0f + __expf(-acc.y));
    o.z = 1.0f / (1.0f + __expf(-acc.z));
    o.w = 1.0f / (1.0f + __expf(-acc.w));
    *(float4*)&out[n + idx] = o;
}

// =========================================================================
extern "C" void kernel_launch(void* const* d_in, const int* in_sizes, int n_in,
                              void* d_out, int out_size)
{
    const float* e1  = (const float*)d_in[0];  // (B,L1,H)
    const float* e2  = (const float*)d_in[1];  // (B,L2,H)
    const float* ipw = (const float*)d_in[2];  // (3H,H)
    const float* ipb = (const float*)d_in[3];  // (3H,)
    const float* W1  = (const float*)d_in[4];  // (H,2H)
    const float* b1  = (const float*)d_in[5];  // (H,)
    const float* W2  = (const float*)d_in[6];  // (1,H)
    const float* b2  = (const float*)d_in[7];  // (1,)
    float* out = (float*)d_out;                // [attn (B,L1,L2)] ++ [match (B,L1,L2)]

    float* P;
    cudaGetSymbolAddress((void**)&P, g_logits);   // reuse logits buffer for partials

    proj_kernel   <<<dim3(HD/64, (BB*LL)/64, 4), 256>>>(e1, e2, ipw, ipb, W1, b1);
    logits_kernel <<<dim3(LL/64, LL/64, BB*NHEAD), 256>>>();
    softmax_mean_kernel<<<BB*LL, 256>>>(W2, out);
    match_partial_kernel<<<dim3(LL/64, LL/64, BB*NSPLIT), 128>>>(W2, P);
    combine_kernel<<<(unsigned)((BB*LL*LL/4 + 255)/256), 256>>>(P, b2, out);
}

// round 12
// speedup vs baseline: 1.2886x; 1.0896x over previous
#include <cuda_runtime.h>
#include <math.h>

#define HD 256      // hidden dim
#define BB 2        // batch
#define LL 512      // seq len (L1 == L2)
#define NHEAD 8
#define DHEAD 32
#define NSPLIT 8    // match channel splits (32 channels each)

// ---------------- scratch (device globals; no allocation) ----------------
__device__ float g_q [BB*LL*HD];                 // 1 MB
__device__ float g_k [BB*LL*HD];                 // 1 MB
__device__ float g_h1[BB*LL*HD];                 // 1 MB (includes +b1)
__device__ float g_h2[BB*LL*HD];                 // 1 MB
__device__ float g_logits[(size_t)BB*NHEAD*LL*LL]; // 16 MB; reused for match partials
__device__ float g_alpha[BB*LL];                 // sum_c (w/2) h1[b,i,c]
__device__ float g_beta [BB*LL];                 // sum_c (w/2) h2[b,j,c]

// ---------------- packed fp32x2 helpers (Blackwell) ----------------
typedef unsigned long long u64p;

__device__ __forceinline__ u64p f2_pack(float lo, float hi) {
    u64p r; asm("mov.b64 %0, {%1, %2};" : "=l"(r) : "f"(lo), "f"(hi)); return r;
}
__device__ __forceinline__ void f2_unpack(u64p p, float& lo, float& hi) {
    asm("mov.b64 {%0, %1}, %2;" : "=f"(lo), "=f"(hi) : "l"(p));
}
__device__ __forceinline__ u64p f2_fma(u64p a, u64p b, u64p c) {
    u64p d; asm("fma.rn.f32x2 %0, %1, %2, %3;" : "=l"(d) : "l"(a), "l"(b), "l"(c)); return d;
}
__device__ __forceinline__ u64p f2_add(u64p a, u64p b) {
    u64p d; asm("add.rn.f32x2 %0, %1, %2;" : "=l"(d) : "l"(a), "l"(b)); return d;
}
__device__ __forceinline__ u64p f2_abs(u64p x) {
    float lo, hi; f2_unpack(x, lo, hi);
    lo = fabsf(lo); hi = fabsf(hi);
    return f2_pack(lo, hi);
}

#define SMS 36   // smem row stride (floats): granule stride 9 (odd) -> conflict-free

// =========================================================================
// K1: projections (K-packed).  job z: 0=q 1=k 2=h1(+b1) 3=h2
// 64x64 tile, 256 threads, 4i x 4j/thread; f32x2 packed along K.
// grid (4, 16, 4) = 256 blocks.
// =========================================================================
__global__ __launch_bounds__(256) void proj_kernel(
    const float* __restrict__ e1, const float* __restrict__ e2,
    const float* __restrict__ ipw, const float* __restrict__ ipb,
    const float* __restrict__ W1,  const float* __restrict__ b1)
{
    const int job = blockIdx.z;
    const float* A; const float* W; const float* bias; int ldw; float* C;
    if (job == 0)      { A = e1; W = ipw;           bias = ipb;      ldw = HD;   C = g_q;  }
    else if (job == 1) { A = e2; W = ipw + HD*HD;   bias = ipb + HD; ldw = HD;   C = g_k;  }
    else if (job == 2) { A = e1; W = W1;            bias = b1;       ldw = 2*HD; C = g_h1; }
    else               { A = e2; W = W1 + HD;       bias = nullptr;  ldw = 2*HD; C = g_h2; }

    const int i0 = blockIdx.y * 64;
    const int j0 = blockIdx.x * 64;

    __shared__ __align__(16) float sA[64][SMS];   // [i-row][k] 32 k used
    __shared__ __align__(16) float sW[64][SMS];   // [j-row][k]

    const int tid = threadIdx.x;
    const int ty = tid >> 4;       // rows i0 + ty*4 + u
    const int tx = tid & 15;       // cols j0 + tx + 16*v

    u64p acc[4][4] = {};   // [u][v], packed over k-parity

    for (int k0 = 0; k0 < HD; k0 += 32) {
        float4 va[2], vw[2];
        int row_[2], kq[2];
#pragma unroll
        for (int r = 0; r < 2; r++) {
            int pidx = tid + r * 256;
            row_[r] = pidx >> 3; kq[r] = (pidx & 7) << 2;
            va[r] = *(const float4*)&A[(size_t)(i0 + row_[r]) * HD  + k0 + kq[r]];
            vw[r] = *(const float4*)&W[(size_t)(j0 + row_[r]) * ldw + k0 + kq[r]];
        }
        __syncthreads();
#pragma unroll
        for (int r = 0; r < 2; r++) {
            *(float4*)&sA[row_[r]][kq[r]] = va[r];
            *(float4*)&sW[row_[r]][kq[r]] = vw[r];
        }
        __syncthreads();

#pragma unroll
        for (int kk4 = 0; kk4 < 32; kk4 += 4) {
            ulonglong2 a[4], w[4];
#pragma unroll
            for (int u = 0; u < 4; u++) a[u] = *(const ulonglong2*)&sA[ty*4 + u][kk4];
#pragma unroll
            for (int v = 0; v < 4; v++) w[v] = *(const ulonglong2*)&sW[tx + 16*v][kk4];
#pragma unroll
            for (int u = 0; u < 4; u++)
#pragma unroll
                for (int v = 0; v < 4; v++) {
                    acc[u][v] = f2_fma(a[u].x, w[v].x, acc[u][v]);
                    acc[u][v] = f2_fma(a[u].y, w[v].y, acc[u][v]);
                }
        }
        __syncthreads();
    }

    float bv[4] = {0.f, 0.f, 0.f, 0.f};
    if (bias) {
#pragma unroll
        for (int v = 0; v < 4; v++) bv[v] = bias[j0 + tx + 16*v];
    }
#pragma unroll
    for (int u = 0; u < 4; u++) {
        const size_t rowoff = (size_t)(i0 + ty*4 + u) * HD + j0 + tx;
#pragma unroll
        for (int v = 0; v < 4; v++) {
            float lo, hi;
            f2_unpack(acc[u][v], lo, hi);
            C[rowoff + 16*v] = lo + hi + bv[v];
        }
    }
}

// =========================================================================
// K2: logits (K-packed). grid (8,8,16); tile 64x64, K=32 single chunk.
// =========================================================================
__global__ __launch_bounds__(256) void logits_kernel()
{
    const int bh = blockIdx.z;
    const int b  = bh >> 3, h = bh & 7;
    const float* Q  = g_q + (size_t)b * LL * HD + h * DHEAD;
    const float* Kp = g_k + (size_t)b * LL * HD + h * DHEAD;
    float* C = g_logits + (size_t)bh * LL * LL;

    const int i0 = blockIdx.y * 64;
    const int j0 = blockIdx.x * 64;

    __shared__ __align__(16) float sQ[64][SMS];
    __shared__ __align__(16) float sK[64][SMS];

    const int tid = threadIdx.x;
    const int ty = tid >> 4;
    const int tx = tid & 15;

    {
        float4 vq[2], vk[2];
        int row_[2], kq[2];
#pragma unroll
        for (int r = 0; r < 2; r++) {
            int pidx = tid + r * 256;
            row_[r] = pidx >> 3; kq[r] = (pidx & 7) << 2;
            vq[r] = *(const float4*)&Q [(size_t)(i0 + row_[r]) * HD + kq[r]];
            vk[r] = *(const float4*)&Kp[(size_t)(j0 + row_[r]) * HD + kq[r]];
        }
#pragma unroll
        for (int r = 0; r < 2; r++) {
            *(float4*)&sQ[row_[r]][kq[r]] = vq[r];
            *(float4*)&sK[row_[r]][kq[r]] = vk[r];
        }
    }
    __syncthreads();

    u64p acc[4][4] = {};
#pragma unroll
    for (int kk4 = 0; kk4 < 32; kk4 += 4) {
        ulonglong2 a[4], w[4];
#pragma unroll
        for (int u = 0; u < 4; u++) a[u] = *(const ulonglong2*)&sQ[ty*4 + u][kk4];
#pragma unroll
        for (int v = 0; v < 4; v++) w[v] = *(const ulonglong2*)&sK[tx + 16*v][kk4];
#pragma unroll
        for (int u = 0; u < 4; u++)
#pragma unroll
            for (int v = 0; v < 4; v++) {
                acc[u][v] = f2_fma(a[u].x, w[v].x, acc[u][v]);
                acc[u][v] = f2_fma(a[u].y, w[v].y, acc[u][v]);
            }
    }

    const float scale = 0.1767766952966369f; // 1/sqrt(32)
#pragma unroll
    for (int u = 0; u < 4; u++) {
        const size_t rowoff = (size_t)(i0 + ty*4 + u) * LL + j0 + tx;
#pragma unroll
        for (int v = 0; v < 4; v++) {
            float lo, hi;
            f2_unpack(acc[u][v], lo, hi);
            C[rowoff + 16*v] = (lo + hi) * scale;
        }
    }
}

// =========================================================================
// K3: softmax + head-mean + alpha/beta (unchanged).
// =========================================================================
__global__ __launch_bounds__(256) void softmax_mean_kernel(
    const float* __restrict__ W2, float* __restrict__ out)
{
    const int b = blockIdx.x >> 9;
    const int i = blockIdx.x & 511;
    const int wid  = threadIdx.x >> 5;
    const int lane = threadIdx.x & 31;
    const int t = threadIdx.x;

    __shared__ float p[8][512];
    __shared__ float reda[8], redb[8];

    const float* row = g_logits + ((size_t)(b*8 + wid) * LL + i) * LL;

    float v[16];
    float mx = -1e30f;
#pragma unroll
    for (int r = 0; r < 16; r++) {
        v[r] = row[lane + 32*r];
        mx = fmaxf(mx, v[r]);
    }
#pragma unroll
    for (int o = 16; o; o >>= 1) mx = fmaxf(mx, __shfl_xor_sync(0xffffffffu, mx, o));

    float s = 0.0f;
#pragma unroll
    for (int r = 0; r < 16; r++) { v[r] = __expf(v[r] - mx); s += v[r]; }
#pragma unroll
    for (int o = 16; o; o >>= 1) s += __shfl_xor_sync(0xffffffffu, s, o);
    const float inv = 1.0f / s;

#pragma unroll
    for (int r = 0; r < 16; r++) p[wid][lane + 32*r] = v[r] * inv;

    {
        const float wh = 0.5f * W2[t];
        float pa = g_h1[((size_t)b*LL + i)*HD + t] * wh;
        float pb = g_h2[((size_t)b*LL + i)*HD + t] * wh;
#pragma unroll
        for (int o = 16; o; o >>= 1) {
            pa += __shfl_xor_sync(0xffffffffu, pa, o);
            pb += __shfl_xor_sync(0xffffffffu, pb, o);
        }
        if (lane == 0) { reda[wid] = pa; redb[wid] = pb; }
    }

    __syncthreads();

    const size_t o = ((size_t)b * LL + i) * LL;
#pragma unroll
    for (int jj = 0; jj < 2; jj++) {
        int j = t + jj * 256;
        float a = 0.0f;
#pragma unroll
        for (int h = 0; h < 8; h++) a += p[h][j];
        out[o + j] = a * 0.125f;
    }

    if (t < 16) {
        float va = (t < 8) ? reda[t] : redb[t - 8];
#pragma unroll
        for (int oo = 4; oo; oo >>= 1) va += __shfl_xor_sync(0xffffffffu, va, oo);
        if (t == 0) g_alpha[b*LL + i] = va;
        if (t == 8) g_beta [b*LL + i] = va;
    }
}

// =========================================================================
// K4: match partials (K-PACKED). 8 splits of 32 channels.
// P[(s*BB+b)*LL*LL + i*LL + j] = sum_{c in split} (w2[c]/2)*|h1[i,c]+h2[j,c]|
// Block tile 64i x 64j, 128 threads, 8i x 4j/thread; acc packed along K.
// Row-major smem; natural LDS.128 k-quads both sides; no duplication.
// grid (8, 8, 16) = 1024 blocks of 4 warps.
// =========================================================================
__global__ __launch_bounds__(128) void match_partial_kernel(
    const float* __restrict__ W2, float* __restrict__ P)
{
    const int bz = blockIdx.z;
    const int b  = bz & 1;
    const int s  = bz >> 1;
    const int i0 = blockIdx.y * 64;
    const int j0 = blockIdx.x * 64;
    const int c0 = s * 32;

    const float* A  = g_h1 + (size_t)b * LL * HD + c0;
    const float* Bm = g_h2 + (size_t)b * LL * HD + c0;

    __shared__ __align__(16) float sA[64][SMS];   // [i-row][k], 32 k used
    __shared__ __align__(16) float sB[64][SMS];   // [j-row][k]
    __shared__ __align__(16) float sw[32];        // w2/2

    const int tid = threadIdx.x;
    const int ty = tid >> 4;       // 0..7  -> rows i0 + ty*8 + u
    const int tx = tid & 15;       // cols j0 + tx + 16*v

    if (tid < 32) sw[tid] = 0.5f * W2[c0 + tid];

    // load tiles: 64 rows x 32 k = 512 float4 each; 128 threads x 4
    {
        float4 va[4], vb[4];
        int rr[4], kq[4];
#pragma unroll
        for (int r = 0; r < 4; r++) {
            int pidx = tid + r * 128;
            rr[r] = pidx >> 3; kq[r] = (pidx & 7) << 2;
            va[r] = *(const float4*)&A [(size_t)(i0 + rr[r]) * HD + kq[r]];
            vb[r] = *(const float4*)&Bm[(size_t)(j0 + rr[r]) * HD + kq[r]];
        }
#pragma unroll
        for (int r = 0; r < 4; r++) {
            *(float4*)&sA[rr[r]][kq[r]] = va[r];
            *(float4*)&sB[rr[r]][kq[r]] = vb[r];
        }
    }
    __syncthreads();

    u64p acc[8][4] = {};   // [u][v], k-packed

#pragma unroll
    for (int k4 = 0; k4 < 32; k4 += 4) {
        const u64p w01 = *(const u64p*)&sw[k4];
        const u64p w23 = *(const u64p*)&sw[k4 + 2];
        ulonglong2 bq[4];
#pragma unroll
        for (int v = 0; v < 4; v++)
            bq[v] = *(const ulonglong2*)&sB[tx + 16*v][k4];
#pragma unroll
        for (int u = 0; u < 8; u++) {
            const ulonglong2 aq = *(const ulonglong2*)&sA[ty*8 + u][k4];
#pragma unroll
            for (int v = 0; v < 4; v++) {
                acc[u][v] = f2_fma(f2_abs(f2_add(aq.x, bq[v].x)), w01, acc[u][v]);
                acc[u][v] = f2_fma(f2_abs(f2_add(aq.y, bq[v].y)), w23, acc[u][v]);
            }
        }
    }

    float* Pd = P + ((size_t)(s*BB + b) * LL * LL);
#pragma unroll
    for (int u = 0; u < 8; u++) {
        const size_t ro = (size_t)(i0 + ty*8 + u) * LL + j0 + tx;
#pragma unroll
        for (int v = 0; v < 4; v++) {
            float lo, hi;
            f2_unpack(acc[u][v], lo, hi);
            Pd[ro + 16*v] = lo + hi;
        }
    }
}

// =========================================================================
// K5: combine: out = sigmoid(alpha_i + beta_j + sum_s P_s + b2)
// =========================================================================
__global__ __launch_bounds__(256) void combine_kernel(
    const float* __restrict__ P, const float* __restrict__ b2,
    float* __restrict__ out)
{
    const size_t n = (size_t)BB * LL * LL;
    const size_t idx = ((size_t)blockIdx.x * 256 + threadIdx.x) * 4;
    if (idx >= n) return;

    const int b = (int)(idx >> 18);
    const int rem = (int)(idx & 262143);
    const int i = rem >> 9;
    const int j = rem & 511;

    float base = g_alpha[b*LL + i] + b2[0];
    float4 bt = *(const float4*)&g_beta[b*LL + j];

    float4 acc = make_float4(base + bt.x, base + bt.y, base + bt.z, base + bt.w);
#pragma unroll
    for (int s = 0; s < NSPLIT; s++) {
        float4 ps = *(const float4*)&P[(size_t)s * n + idx];
        acc.x += ps.x; acc.y += ps.y; acc.z += ps.z; acc.w += ps.w;
    }
    float4 o;
    o.x = 1.0f / (1.0f + __expf(-acc.x));
    o.y = 1.0f / (1.0f + __expf(-acc.y));
    o.z = 1.0f / (1.0f + __expf(-acc.z));
    o.w = 1.0f / (1.0f + __expf(-acc.w));
    *(float4*)&out[n + idx] = o;
}

// =========================================================================
extern "C" void kernel_launch(void* const* d_in, const int* in_sizes, int n_in,
                              void* d_out, int out_size)
{
    const float* e1  = (const float*)d_in[0];  // (B,L1,H)
    const float* e2  = (const float*)d_in[1];  // (B,L2,H)
    const float* ipw = (const float*)d_in[2];  // (3H,H)
    const float* ipb = (const float*)d_in[3];  // (3H,)
    const float* W1  = (const float*)d_in[4];  // (H,2H)
    const float* b1  = (const float*)d_in[5];  // (H,)
    const float* W2  = (const float*)d_in[6];  // (1,H)
    const float* b2  = (const float*)d_in[7];  // (1,)
    float* out = (float*)d_out;                // [attn (B,L1,L2)] ++ [match (B,L1,L2)]

    float* P;
    cudaGetSymbolAddress((void**)&P, g_logits);   // reuse logits buffer for partials

    proj_kernel   <<<dim3(HD/64, (BB*LL)/64, 4), 256>>>(e1, e2, ipw, ipb, W1, b1);
    logits_kernel <<<dim3(LL/64, LL/64, BB*NHEAD), 256>>>();
    softmax_mean_kernel<<<BB*LL, 256>>>(W2, out);
    match_partial_kernel<<<dim3(LL/64, LL/64, BB*NSPLIT), 128>>>(W2, P);
    combine_kernel<<<(unsigned)((BB*LL*LL/4 + 255)/256), 256>>>(P, b2, out);
}

// round 13
// speedup vs baseline: 1.3860x; 1.0756x over previous
#include <cuda_runtime.h>
#include <math.h>

#define HD 256      // hidden dim
#define BB 2        // batch
#define LL 512      // seq len (L1 == L2)
#define NHEAD 8
#define DHEAD 32
#define NSPLIT 8    // match channel splits (32 channels each)

// ---------------- scratch (device globals; no allocation) ----------------
__device__ float g_q [BB*LL*HD];                 // 1 MB
__device__ float g_k [BB*LL*HD];                 // 1 MB
__device__ float g_h1[BB*LL*HD];                 // 1 MB (includes +b1)
__device__ float g_h2[BB*LL*HD];                 // 1 MB
__device__ float g_logits[(size_t)BB*NHEAD*LL*LL]; // 16 MB logits
__device__ float g_part[(size_t)NSPLIT*BB*LL*LL];  // 16 MB match partials
__device__ float g_alpha[BB*LL];                 // sum_c (w/2) h1[b,i,c]
__device__ float g_beta [BB*LL];                 // sum_c (w/2) h2[b,j,c]

// ---------------- packed fp32x2 helpers (Blackwell) ----------------
typedef unsigned long long u64p;

__device__ __forceinline__ u64p f2_pack(float lo, float hi) {
    u64p r; asm("mov.b64 %0, {%1, %2};" : "=l"(r) : "f"(lo), "f"(hi)); return r;
}
__device__ __forceinline__ void f2_unpack(u64p p, float& lo, float& hi) {
    asm("mov.b64 {%0, %1}, %2;" : "=f"(lo), "=f"(hi) : "l"(p));
}
__device__ __forceinline__ u64p f2_fma(u64p a, u64p b, u64p c) {
    u64p d; asm("fma.rn.f32x2 %0, %1, %2, %3;" : "=l"(d) : "l"(a), "l"(b), "l"(c)); return d;
}
__device__ __forceinline__ u64p f2_add(u64p a, u64p b) {
    u64p d; asm("add.rn.f32x2 %0, %1, %2;" : "=l"(d) : "l"(a), "l"(b)); return d;
}
__device__ __forceinline__ u64p f2_abs(u64p x) {
    float lo, hi; f2_unpack(x, lo, hi);
    lo = fabsf(lo); hi = fabsf(hi);
    return f2_pack(lo, hi);
}

#define SMS 36   // smem row stride (floats): granule stride 9 (odd) -> conflict-free

// =========================================================================
// K1: projections (K-packed).  job z: 0=q 1=k 2=h1(+b1) 3=h2
// 64x64 tile, 256 threads, 4i x 4j/thread; f32x2 packed along K.
// grid (4, 16, 4) = 256 blocks.
// =========================================================================
__global__ __launch_bounds__(256) void proj_kernel(
    const float* __restrict__ e1, const float* __restrict__ e2,
    const float* __restrict__ ipw, const float* __restrict__ ipb,
    const float* __restrict__ W1,  const float* __restrict__ b1)
{
    const int job = blockIdx.z;
    const float* A; const float* W; const float* bias; int ldw; float* C;
    if (job == 0)      { A = e1; W = ipw;           bias = ipb;      ldw = HD;   C = g_q;  }
    else if (job == 1) { A = e2; W = ipw + HD*HD;   bias = ipb + HD; ldw = HD;   C = g_k;  }
    else if (job == 2) { A = e1; W = W1;            bias = b1;       ldw = 2*HD; C = g_h1; }
    else               { A = e2; W = W1 + HD;       bias = nullptr;  ldw = 2*HD; C = g_h2; }

    const int i0 = blockIdx.y * 64;
    const int j0 = blockIdx.x * 64;

    __shared__ __align__(16) float sA[64][SMS];   // [i-row][k] 32 k used
    __shared__ __align__(16) float sW[64][SMS];   // [j-row][k]

    const int tid = threadIdx.x;
    const int ty = tid >> 4;       // rows i0 + ty*4 + u
    const int tx = tid & 15;       // cols j0 + tx + 16*v

    u64p acc[4][4] = {};   // [u][v], packed over k-parity

    for (int k0 = 0; k0 < HD; k0 += 32) {
        float4 va[2], vw[2];
        int row_[2], kq[2];
#pragma unroll
        for (int r = 0; r < 2; r++) {
            int pidx = tid + r * 256;
            row_[r] = pidx >> 3; kq[r] = (pidx & 7) << 2;
            va[r] = *(const float4*)&A[(size_t)(i0 + row_[r]) * HD  + k0 + kq[r]];
            vw[r] = *(const float4*)&W[(size_t)(j0 + row_[r]) * ldw + k0 + kq[r]];
        }
        __syncthreads();
#pragma unroll
        for (int r = 0; r < 2; r++) {
            *(float4*)&sA[row_[r]][kq[r]] = va[r];
            *(float4*)&sW[row_[r]][kq[r]] = vw[r];
        }
        __syncthreads();

#pragma unroll
        for (int kk4 = 0; kk4 < 32; kk4 += 4) {
            ulonglong2 a[4], w[4];
#pragma unroll
            for (int u = 0; u < 4; u++) a[u] = *(const ulonglong2*)&sA[ty*4 + u][kk4];
#pragma unroll
            for (int v = 0; v < 4; v++) w[v] = *(const ulonglong2*)&sW[tx + 16*v][kk4];
#pragma unroll
            for (int u = 0; u < 4; u++)
#pragma unroll
                for (int v = 0; v < 4; v++) {
                    acc[u][v] = f2_fma(a[u].x, w[v].x, acc[u][v]);
                    acc[u][v] = f2_fma(a[u].y, w[v].y, acc[u][v]);
                }
        }
        __syncthreads();
    }

    float bv[4] = {0.f, 0.f, 0.f, 0.f};
    if (bias) {
#pragma unroll
        for (int v = 0; v < 4; v++) bv[v] = bias[j0 + tx + 16*v];
    }
#pragma unroll
    for (int u = 0; u < 4; u++) {
        const size_t rowoff = (size_t)(i0 + ty*4 + u) * HD + j0 + tx;
#pragma unroll
        for (int v = 0; v < 4; v++) {
            float lo, hi;
            f2_unpack(acc[u][v], lo, hi);
            C[rowoff + 16*v] = lo + hi + bv[v];
        }
    }
}

// =========================================================================
// K2 (FUSED): logits tiles (z<16) + match partial tiles (z>=16).
// Both: 64x64 tile, 128 threads, 8i x 4j/thread, f32x2 packed along K.
// grid (8, 8, 32) = 2048 blocks of 4 warps.
//
// logits[b,h,i,j] = (1/sqrt(32)) * sum_d q*k             (z = b*8+h)
// P[(s*BB+b)...]  = sum_{c in split s} (w2[c]/2)*|h1+h2| (z-16 = s*2+b)
// =========================================================================
__global__ __launch_bounds__(128) void mid_kernel(
    const float* __restrict__ W2, float* __restrict__ P)
{
    const int z  = blockIdx.z;
    const int i0 = blockIdx.y * 64;
    const int j0 = blockIdx.x * 64;

    __shared__ __align__(16) float sA[64][SMS];   // [i-row][k], 32 k used
    __shared__ __align__(16) float sB[64][SMS];   // [j-row][k]
    __shared__ __align__(16) float sw[32];        // w2/2 (match only)

    const int tid = threadIdx.x;
    const int ty = tid >> 4;       // 0..7  -> rows i0 + ty*8 + u
    const int tx = tid & 15;       // cols j0 + tx + 16*v

    const bool is_logits = (z < 16);

    const float* Ag;
    const float* Bg;
    if (is_logits) {
        const int b = z >> 3, h = z & 7;
        Ag = g_q + (size_t)b * LL * HD + h * DHEAD;
        Bg = g_k + (size_t)b * LL * HD + h * DHEAD;
    } else {
        const int bz = z - 16;
        const int b  = bz & 1;
        const int s  = bz >> 1;
        const int c0 = s * 32;
        Ag = g_h1 + (size_t)b * LL * HD + c0;
        Bg = g_h2 + (size_t)b * LL * HD + c0;
        if (tid < 32) sw[tid] = 0.5f * W2[c0 + tid];
    }

    // load tiles: 64 rows x 32 k = 512 float4 each; 128 threads x 4
    {
        float4 va[4], vb[4];
        int rr[4], kq[4];
#pragma unroll
        for (int r = 0; r < 4; r++) {
            int pidx = tid + r * 128;
            rr[r] = pidx >> 3; kq[r] = (pidx & 7) << 2;
            va[r] = *(const float4*)&Ag[(size_t)(i0 + rr[r]) * HD + kq[r]];
            vb[r] = *(const float4*)&Bg[(size_t)(j0 + rr[r]) * HD + kq[r]];
        }
#pragma unroll
        for (int r = 0; r < 4; r++) {
            *(float4*)&sA[rr[r]][kq[r]] = va[r];
            *(float4*)&sB[rr[r]][kq[r]] = vb[r];
        }
    }
    __syncthreads();

    u64p acc[8][4] = {};   // [u][v], k-packed

    if (is_logits) {
#pragma unroll
        for (int k4 = 0; k4 < 32; k4 += 4) {
            ulonglong2 bq[4];
#pragma unroll
            for (int v = 0; v < 4; v++)
                bq[v] = *(const ulonglong2*)&sB[tx + 16*v][k4];
#pragma unroll
            for (int u = 0; u < 8; u++) {
                const ulonglong2 aq = *(const ulonglong2*)&sA[ty*8 + u][k4];
#pragma unroll
                for (int v = 0; v < 4; v++) {
                    acc[u][v] = f2_fma(aq.x, bq[v].x, acc[u][v]);
                    acc[u][v] = f2_fma(aq.y, bq[v].y, acc[u][v]);
                }
            }
        }
        const float scale = 0.1767766952966369f; // 1/sqrt(32)
        float* C = g_logits + (size_t)z * LL * LL;
#pragma unroll
        for (int u = 0; u < 8; u++) {
            const size_t ro = (size_t)(i0 + ty*8 + u) * LL + j0 + tx;
#pragma unroll
            for (int v = 0; v < 4; v++) {
                float lo, hi;
                f2_unpack(acc[u][v], lo, hi);
                C[ro + 16*v] = (lo + hi) * scale;
            }
        }
    } else {
#pragma unroll
        for (int k4 = 0; k4 < 32; k4 += 4) {
            const u64p w01 = *(const u64p*)&sw[k4];
            const u64p w23 = *(const u64p*)&sw[k4 + 2];
            ulonglong2 bq[4];
#pragma unroll
            for (int v = 0; v < 4; v++)
                bq[v] = *(const ulonglong2*)&sB[tx + 16*v][k4];
#pragma unroll
            for (int u = 0; u < 8; u++) {
                const ulonglong2 aq = *(const ulonglong2*)&sA[ty*8 + u][k4];
#pragma unroll
                for (int v = 0; v < 4; v++) {
                    acc[u][v] = f2_fma(f2_abs(f2_add(aq.x, bq[v].x)), w01, acc[u][v]);
                    acc[u][v] = f2_fma(f2_abs(f2_add(aq.y, bq[v].y)), w23, acc[u][v]);
                }
            }
        }
        float* Pd = P + (size_t)(z - 16) * LL * LL;   // plane order: s*BB+b == (z-16) reindexed below
        // note: z-16 = s*2 + b, and plane index used by combine is s*BB + b = same value.
#pragma unroll
        for (int u = 0; u < 8; u++) {
            const size_t ro = (size_t)(i0 + ty*8 + u) * LL + j0 + tx;
#pragma unroll
            for (int v = 0; v < 4; v++) {
                float lo, hi;
                f2_unpack(acc[u][v], lo, hi);
                Pd[ro + 16*v] = lo + hi;
            }
        }
    }
}

// =========================================================================
// K3: softmax + head-mean + alpha/beta (unchanged).
// =========================================================================
__global__ __launch_bounds__(256) void softmax_mean_kernel(
    const float* __restrict__ W2, float* __restrict__ out)
{
    const int b = blockIdx.x >> 9;
    const int i = blockIdx.x & 511;
    const int wid  = threadIdx.x >> 5;
    const int lane = threadIdx.x & 31;
    const int t = threadIdx.x;

    __shared__ float p[8][512];
    __shared__ float reda[8], redb[8];

    const float* row = g_logits + ((size_t)(b*8 + wid) * LL + i) * LL;

    float v[16];
    float mx = -1e30f;
#pragma unroll
    for (int r = 0; r < 16; r++) {
        v[r] = row[lane + 32*r];
        mx = fmaxf(mx, v[r]);
    }
#pragma unroll
    for (int o = 16; o; o >>= 1) mx = fmaxf(mx, __shfl_xor_sync(0xffffffffu, mx, o));

    float s = 0.0f;
#pragma unroll
    for (int r = 0; r < 16; r++) { v[r] = __expf(v[r] - mx); s += v[r]; }
#pragma unroll
    for (int o = 16; o; o >>= 1) s += __shfl_xor_sync(0xffffffffu, s, o);
    const float inv = 1.0f / s;

#pragma unroll
    for (int r = 0; r < 16; r++) p[wid][lane + 32*r] = v[r] * inv;

    {
        const float wh = 0.5f * W2[t];
        float pa = g_h1[((size_t)b*LL + i)*HD + t] * wh;
        float pb = g_h2[((size_t)b*LL + i)*HD + t] * wh;
#pragma unroll
        for (int o = 16; o; o >>= 1) {
            pa += __shfl_xor_sync(0xffffffffu, pa, o);
            pb += __shfl_xor_sync(0xffffffffu, pb, o);
        }
        if (lane == 0) { reda[wid] = pa; redb[wid] = pb; }
    }

    __syncthreads();

    const size_t o = ((size_t)b * LL + i) * LL;
#pragma unroll
    for (int jj = 0; jj < 2; jj++) {
        int j = t + jj * 256;
        float a = 0.0f;
#pragma unroll
        for (int h = 0; h < 8; h++) a += p[h][j];
        out[o + j] = a * 0.125f;
    }

    if (t < 16) {
        float va = (t < 8) ? reda[t] : redb[t - 8];
#pragma unroll
        for (int oo = 4; oo; oo >>= 1) va += __shfl_xor_sync(0xffffffffu, va, oo);
        if (t == 0) g_alpha[b*LL + i] = va;
        if (t == 8) g_beta [b*LL + i] = va;
    }
}

// =========================================================================
// K5: combine: out = sigmoid(alpha_i + beta_j + sum_s P_s + b2)
// P plane index: z-16 = s*2+b; combine iterates planes 0..15 directly.
// =========================================================================
__global__ __launch_bounds__(256) void combine_kernel(
    const float* __restrict__ P, const float* __restrict__ b2,
    float* __restrict__ out)
{
    const size_t n  = (size_t)LL * LL;          // per (plane) elements
    const size_t nn = (size_t)BB * LL * LL;
    const size_t idx = ((size_t)blockIdx.x * 256 + threadIdx.x) * 4;
    if (idx >= nn) return;

    const int b = (int)(idx >> 18);
    const int rem = (int)(idx & 262143);
    const int i = rem >> 9;
    const int j = rem & 511;

    float base = g_alpha[b*LL + i] + b2[0];
    float4 bt = *(const float4*)&g_beta[b*LL + j];

    float4 acc = make_float4(base + bt.x, base + bt.y, base + bt.z, base + bt.w);
    const size_t pix = (size_t)rem;             // offset within a (b) plane pair
#pragma unroll
    for (int s = 0; s < NSPLIT; s++) {
        // plane for (s, b) is index s*2 + b
        float4 ps = *(const float4*)&P[((size_t)(s*2 + b)) * n + pix];
        acc.x += ps.x; acc.y += ps.y; acc.z += ps.z; acc.w += ps.w;
    }
    float4 o;
    o.x = 1.0f / (1.0f + __expf(-acc.x));
    o.y = 1.0f / (1.0f + __expf(-acc.y));
    o.z = 1.0f / (1.0f + __expf(-acc.z));
    o.w = 1.0f / (1.0f + __expf(-acc.w));
    *(float4*)&out[nn + idx] = o;
}

// =========================================================================
extern "C" void kernel_launch(void* const* d_in, const int* in_sizes, int n_in,
                              void* d_out, int out_size)
{
    const float* e1  = (const float*)d_in[0];  // (B,L1,H)
    const float* e2  = (const float*)d_in[1];  // (B,L2,H)
    const float* ipw = (const float*)d_in[2];  // (3H,H)
    const float* ipb = (const float*)d_in[3];  // (3H,)
    const float* W1  = (const float*)d_in[4];  // (H,2H)
    const float* b1  = (const float*)d_in[5];  // (H,)
    const float* W2  = (const float*)d_in[6];  // (1,H)
    const float* b2  = (const float*)d_in[7];  // (1,)
    float* out = (float*)d_out;                // [attn (B,L1,L2)] ++ [match (B,L1,L2)]

    float* P;
    cudaGetSymbolAddress((void**)&P, g_part);

    proj_kernel <<<dim3(HD/64, (BB*LL)/64, 4), 256>>>(e1, e2, ipw, ipb, W1, b1);
    mid_kernel  <<<dim3(LL/64, LL/64, 32), 128>>>(W2, P);
    softmax_mean_kernel<<<BB*LL, 256>>>(W2, out);
    combine_kernel<<<(unsigned)((BB*LL*LL/4 + 255)/256), 256>>>(P, b2, out);
}